// round 16
// baseline (speedup 1.0000x reference)
#include <cuda_runtime.h>
#include <cuda_fp16.h>
#include <math.h>
#include <stdint.h>

#define NN 200000
#define EE 1000000
#define INF 128
#define OUTF 128
#define HH 4
#define DKK 32
#define TILES 1563            // ceil(NN/128)

// smem layout (bytes): rows padded to 272B (conflict-free LDSM)
#define ROWB 272
#define A_HI_OFF 0
#define B_OFF    34816        // B right after A_HI (1-term GEMMs everywhere)
#define SMEM_TOT 69632

// ---------------- scratch (device globals; no allocation) ----------------
__device__ __half g_KMh[(size_t)2*NN*2*OUTF];   // K/M interleaved fp16: [2N][2][128]
__device__ __half g_Qh [(size_t)2*NN*OUTF];     // fp16
__device__ __half g_aggh[(size_t)2*NN*OUTF];    // fp16 aggregation buffer
__device__ float  g_den[(size_t)2*NN*HH];       // f32 softmax denominators
__device__ float  g_WkA[2*INF*OUTF];
__device__ float  g_bkA[2*OUTF];
__device__ float  g_WmM[2*INF*OUTF];
__device__ float  g_bmM[2*OUTF];
// packed fp16 weights, W^T layout [o][k]: [mat(4)][type(2)][128*128]
__device__ __half g_Wh[(size_t)4*2*16384];
// exact-dst sorted edges: srcs only, grouped by destination node (d-major)
__device__ uint32_t g_srt[(size_t)2*EE];
__device__ int    g_hist[2*NN];
__device__ int    g_cursor[2*NN + 1];
__device__ int    g_cur2[2*NN];
__device__ int    g_bsum[512];
__device__ int    g_bsumx[512];

#define MMA16816F16(acc, A0,A1,A2,A3, B0,B1) \
  asm volatile("mma.sync.aligned.m16n8k16.row.col.f32.f16.f16.f32 " \
    "{%0,%1,%2,%3}, {%4,%5,%6,%7}, {%8,%9}, {%0,%1,%2,%3};" \
    : "+f"((acc)[0]), "+f"((acc)[1]), "+f"((acc)[2]), "+f"((acc)[3]) \
    : "r"(A0), "r"(A1), "r"(A2), "r"(A3), "r"(B0), "r"(B1))

#define LDSM4(r0,r1,r2,r3,addr) \
  asm volatile("ldmatrix.sync.aligned.m8n8.x4.shared.b16 {%0,%1,%2,%3}, [%4];" \
    : "=r"(r0), "=r"(r1), "=r"(r2), "=r"(r3) : "r"(addr))

__device__ __forceinline__ uint32_t smem_u32(const void* p) {
    uint32_t a;
    asm("{ .reg .u64 t; cvta.to.shared.u64 t, %1; cvt.u32.u64 %0, t; }" : "=r"(a) : "l"(p));
    return a;
}

// ---------------- prep: fold w_att/w_msg (+ mu*scale) into projection weights
__global__ void prep_fold(const float* __restrict__ Wk, const float* __restrict__ bk,
                          const float* __restrict__ Wm, const float* __restrict__ bm,
                          const float* __restrict__ w_att, const float* __restrict__ w_msg,
                          const float* __restrict__ mu) {
    int idx = blockIdx.x*blockDim.x + threadIdx.x;     // 65536
    const int total = 2*INF*OUTF;
    int m   = idx / total;
    int rem = idx - m*total;
    int t   = rem / (INF*OUTF);
    int io  = rem - t*(INF*OUTF);
    int i   = io / OUTF;
    int o   = io - i*OUTF;
    int h   = o >> 5, f = o & 31;

    const float* W = m ? Wm : Wk;
    const float* R = m ? w_msg : w_att;
    const float* wrow = W + ((size_t)t*INF + i)*OUTF + h*DKK;
    const float* rr   = R + (((size_t)t*HH + h)*DKK)*DKK + f;
    float s = 0.f;
    #pragma unroll
    for (int d = 0; d < DKK; d++) s += wrow[d] * rr[(size_t)d*DKK];
    float fold = m ? 1.f : mu[t*HH + h] * 0.17677669529663687f;   // mu / sqrt(DK)
    (m ? g_WmM : g_WkA)[(size_t)t*INF*OUTF + io] = s * fold;

    if (i == 0) {
        const float* b = m ? bm : bk;
        float sb = 0.f;
        #pragma unroll
        for (int d = 0; d < DKK; d++) sb += b[t*OUTF + h*DKK + d] * rr[(size_t)d*DKK];
        (m ? g_bmM : g_bkA)[t*OUTF + o] = sb * fold;
    }
}

// pack 4 matrices (Kfold, Mfold, Q, A) per type as W^T [o][k] fp16; also zero hist
__global__ void prep_pack(const float* __restrict__ Wq, const float* __restrict__ Wa) {
    int idx = blockIdx.x*blockDim.x + threadIdx.x;   // 131072
    int mat = idx >> 15;
    int rem = idx & 32767;
    int t   = rem >> 14;
    int ok  = rem & 16383;
    int o   = ok >> 7;
    int k   = ok & 127;
    const float* W = (mat==0) ? g_WkA : (mat==1) ? g_WmM : (mat==2) ? Wq : Wa;
    float v = W[((size_t)t*INF + k)*OUTF + o];
    g_Wh[(size_t)(mat*2 + t)*16384 + ok] = __float2half(v);
    // zero per-dst histogram (grid-stride over 2N)
    for (int z = idx; z < 2*NN; z += 131072) g_hist[z] = 0;
}

// ---------------- exact-dst bucketing: histogram -> 2-level scan -> scatter ----
__global__ void hist_kernel(const int* __restrict__ ei) {
    int i = blockIdx.x*blockDim.x + threadIdx.x;
    if (i >= 2*EE) return;
    int t = i >= EE;
    int e = i - t*EE;
    int dst = ei[(size_t)t*2*EE + EE + e];
    atomicAdd(&g_hist[(1-t)*NN + dst], 1);     // node key = d*NN + dst
}

__global__ void scan_blocks() {                // 391 blocks x 1024
    __shared__ int ss[1024];
    int tid = threadIdx.x;
    int gi = blockIdx.x*1024 + tid;
    int v = (gi < 2*NN) ? g_hist[gi] : 0;
    ss[tid] = v;
    __syncthreads();
    for (int off = 1; off < 1024; off <<= 1) {
        int u = (tid >= off) ? ss[tid-off] : 0;
        __syncthreads();
        ss[tid] += u;
        __syncthreads();
    }
    if (gi < 2*NN) g_cursor[gi] = ss[tid] - v;   // exclusive within block
    if (tid == 1023) g_bsum[blockIdx.x] = ss[1023];
}

__global__ void scan_tops() {                  // 1 block x 512 (covers 391 block sums)
    __shared__ int ss[512];
    int tid = threadIdx.x;
    int v = (tid < 391) ? g_bsum[tid] : 0;
    ss[tid] = v;
    __syncthreads();
    for (int off = 1; off < 512; off <<= 1) {
        int u = (tid >= off) ? ss[tid-off] : 0;
        __syncthreads();
        ss[tid] += u;
        __syncthreads();
    }
    g_bsumx[tid] = ss[tid] - v;                // exclusive
}

__global__ void add_offs() {                   // 391 blocks x 1024
    int tid = threadIdx.x;
    int gi = blockIdx.x*1024 + tid;
    if (gi < 2*NN) {
        int c = g_cursor[gi] + g_bsumx[blockIdx.x];
        g_cursor[gi] = c;
        g_cur2[gi]   = c;
    }
    if (gi == 0) g_cursor[2*NN] = 2*EE;
}

__global__ void scatter_kernel(const int* __restrict__ ei) {
    int i = blockIdx.x*blockDim.x + threadIdx.x;
    if (i >= 2*EE) return;
    int t = i >= EE;
    int e = i - t*EE;
    int src = ei[(size_t)t*2*EE + e];
    int dst = ei[(size_t)t*2*EE + EE + e];
    int pos = atomicAdd(&g_cur2[(1-t)*NN + dst], 1);
    g_srt[pos] = (uint32_t)src;
}

// copy one packed fp16 weight matrix (32KB) into the padded B buffer
__device__ __forceinline__ void copy_B(char* sm, int mat, int nt, int tid) {
    const uint4* src = (const uint4*)(g_Wh + (size_t)(mat*2 + nt) * 16384);
    #pragma unroll 2
    for (int i = tid; i < 2048; i += 256) {
        int row = i >> 4, chunk = i & 15;
        *(uint4*)(sm + B_OFF + row*ROWB + chunk*16) = src[i];
    }
}

// 1-term fp16 GEMM: acc += A*B
__device__ __forceinline__ void gemm_1term(uint32_t su, int w, int lane, float acc[2][8][4]) {
    int wm = w & 3, wn = w >> 2;
    int mat = lane >> 3, r8 = lane & 7;
    uint32_t aoff = (uint32_t)(wm*32 + (mat&1)*8 + r8)*ROWB + (mat>>1)*16;
    uint32_t boff = (uint32_t)(wn*64 + (mat>>1)*8 + r8)*ROWB + (mat&1)*16 + B_OFF;

    #pragma unroll
    for (int kk = 0; kk < 8; kk++) {
        uint32_t kb = kk*32;
        uint32_t A[2][4], B[8][2];
        #pragma unroll
        for (int mt = 0; mt < 2; mt++) {
            uint32_t ao = aoff + mt*16*ROWB + kb;
            LDSM4(A[mt][0], A[mt][1], A[mt][2], A[mt][3], su + A_HI_OFF + ao);
        }
        #pragma unroll
        for (int p = 0; p < 4; p++) {
            uint32_t bo = boff + p*16*ROWB + kb;
            LDSM4(B[2*p][0], B[2*p][1], B[2*p+1][0], B[2*p+1][1], su + bo);
        }
        #pragma unroll
        for (int mt = 0; mt < 2; mt++)
            #pragma unroll
            for (int nt = 0; nt < 8; nt++)
                MMA16816F16(acc[mt][nt], A[mt][0],A[mt][1],A[mt][2],A[mt][3], B[nt][0],B[nt][1]);
    }
}

// ---------------- proj: Ktr, Mtr, Q via 1-term mma.sync -> fp16 tables ----------------
__global__ void __launch_bounds__(256, 2) proj_mma_kernel(const float* __restrict__ x,
                                                          const float* __restrict__ bq) {
    extern __shared__ char sm[];
    uint32_t su = smem_u32(sm);
    int tid = threadIdx.x;
    int w = tid >> 5, lane = tid & 31;
    int wm = w & 3, wn = w >> 2;

    int blk = blockIdx.x;
    int ntp = blk >= TILES;
    int tb  = blk - ntp*TILES;
    int base = tb*128; if (base > NN-128) base = NN-128;
    size_t nbase = (size_t)ntp*NN + base;

    // stage A: x rows -> fp16 smem (single-rounded)
    #pragma unroll 4
    for (int j = 0; j < 16; j++) {
        int idx = tid + j*256;             // 4096 float4
        int row = idx >> 5, c4 = idx & 31;
        float4 v = ((const float4*)(x + (nbase + row)*INF))[c4];
        __half2 h01 = __floats2half2_rn(v.x, v.y);
        __half2 h23 = __floats2half2_rn(v.z, v.w);
        *(uint32_t*)(sm + A_HI_OFF + row*ROWB + c4*8)     = *reinterpret_cast<uint32_t*>(&h01);
        *(uint32_t*)(sm + A_HI_OFF + row*ROWB + c4*8 + 4) = *reinterpret_cast<uint32_t*>(&h23);
    }

    for (int m = 0; m < 3; m++) {
        __syncthreads();
        copy_B(sm, m, ntp, tid);
        __syncthreads();

        const float* bias = (m==0) ? g_bkA + ntp*OUTF
                          : (m==1) ? g_bmM + ntp*OUTF
                                   : bq    + ntp*OUTF;
        float acc[2][8][4];
        #pragma unroll
        for (int mt = 0; mt < 2; mt++)
            #pragma unroll
            for (int nt = 0; nt < 8; nt++) {
                int col = wn*64 + nt*8 + 2*(lane & 3);
                float b0 = bias[col], b1 = bias[col+1];
                acc[mt][nt][0] = b0; acc[mt][nt][1] = b1;
                acc[mt][nt][2] = b0; acc[mt][nt][3] = b1;
            }
        gemm_1term(su, w, lane, acc);
        __syncthreads();   // all warps done with B before staging reuses it

        // stage fp16 result into B buffer: 128 rows x 256B (+ ROWB pad)
        __half* H = (__half*)(sm + B_OFF);
        #pragma unroll
        for (int mt = 0; mt < 2; mt++)
            #pragma unroll
            for (int nt = 0; nt < 8; nt++) {
                int row = wm*32 + mt*16 + (lane >> 2);
                int col = wn*64 + nt*8 + 2*(lane & 3);
                *(__half2*)((char*)H + row*ROWB + col*2) =
                    __floats2half2_rn(acc[mt][nt][0], acc[mt][nt][1]);
                *(__half2*)((char*)H + (row+8)*ROWB + col*2) =
                    __floats2half2_rn(acc[mt][nt][2], acc[mt][nt][3]);
            }
        __syncthreads();

        // coalesced copy-out: 128 rows x 256B
        #pragma unroll
        for (int i = tid; i < 2048; i += 256) {
            int row = i >> 4, ch = i & 15;
            uint4 v = *(uint4*)((char*)H + row*ROWB + ch*16);
            __half* dst = (m == 2) ? g_Qh + (nbase + row)*OUTF + ch*8
                                   : g_KMh + ((nbase + row)*2 + m)*OUTF + ch*8;
            *(uint4*)dst = v;
        }
    }
}

// ---- edge pass: warp/dst-node, uint4 KM gather (K lanes 0-15, M lanes 16-31),
//      2 edges/iter 2-slot pipeline ----
__global__ void __launch_bounds__(256) edge_node_kernel() {
    int wid  = (blockIdx.x*blockDim.x + threadIdx.x) >> 5;   // node id [0, 2N)
    int lane = threadIdx.x & 31;
    if (wid >= 2*NN) return;
    int d = wid >= NN;
    int s = 1 - d;

    int start = g_cursor[wid];
    int end   = g_cursor[wid + 1];

    if (start == end) {   // empty segment: zeros
        if (lane >= 16)
            ((uint4*)(g_aggh + (size_t)wid*OUTF))[lane - 16] = make_uint4(0u,0u,0u,0u);
        if (lane < 16 && (lane & 3) == 0)
            g_den[(size_t)wid*HH + (lane >> 2)] = 0.f;
        return;
    }

    // q elements [8*(lane&15), +8) — meaningful for K lanes
    uint4 qv = ((const uint4*)(g_Qh + (size_t)wid*OUTF))[lane & 15];
    float qf[8];
    {
        float2 t0 = __half22float2(*(const __half2*)&qv.x);
        float2 t1 = __half22float2(*(const __half2*)&qv.y);
        float2 t2 = __half22float2(*(const __half2*)&qv.z);
        float2 t3 = __half22float2(*(const __half2*)&qv.w);
        qf[0]=t0.x; qf[1]=t0.y; qf[2]=t1.x; qf[3]=t1.y;
        qf[4]=t2.x; qf[5]=t2.y; qf[6]=t3.x; qf[7]=t3.y;
    }

    float accf[8] = {0,0,0,0,0,0,0,0};
    float den = 0.f;
    int srcLane = ((lane & 15) >> 2) << 2;   // head-base K lane for this lane's elements

    const __half* KMbase = g_KMh + (size_t)s*NN*2*OUTF;   // rows of 256 halves (K|M)

    uint4 c0, c1;
    {
        int sc0 = (int)g_srt[start];
        c0 = ((const uint4*)(KMbase + (size_t)sc0*2*OUTF))[lane];
        if (start + 1 < end) {
            int sc1 = (int)g_srt[start + 1];
            c1 = ((const uint4*)(KMbase + (size_t)sc1*2*OUTF))[lane];
        }
    }

    for (int i = start; i < end; i += 2) {
        uint4 e0 = c0, e1 = c1;
        bool has1 = (i + 1 < end);
        if (i + 2 < end) {
            int sc0 = (int)g_srt[i + 2];
            c0 = ((const uint4*)(KMbase + (size_t)sc0*2*OUTF))[lane];
            if (i + 3 < end) {
                int sc1 = (int)g_srt[i + 3];
                c1 = ((const uint4*)(KMbase + (size_t)sc1*2*OUTF))[lane];
            }
        }

        #pragma unroll
        for (int which = 0; which < 2; which++) {
            if (which == 1 && !has1) break;
            uint4 e = (which == 0) ? e0 : e1;
            float f[8];
            {
                float2 t0 = __half22float2(*(const __half2*)&e.x);
                float2 t1 = __half22float2(*(const __half2*)&e.y);
                float2 t2 = __half22float2(*(const __half2*)&e.z);
                float2 t3 = __half22float2(*(const __half2*)&e.w);
                f[0]=t0.x; f[1]=t0.y; f[2]=t1.x; f[3]=t1.y;
                f[4]=t2.x; f[5]=t2.y; f[6]=t3.x; f[7]=t3.y;
            }
            // K lanes: partial dot over 8 elements
            float p = f[0]*qf[0] + f[1]*qf[1] + f[2]*qf[2] + f[3]*qf[3]
                    + f[4]*qf[4] + f[5]*qf[5] + f[6]*qf[6] + f[7]*qf[7];
            p += __shfl_down_sync(0xffffffffu, p, 2, 4);
            p += __shfl_down_sync(0xffffffffu, p, 1, 4);
            float att = __shfl_sync(0xffffffffu, p, srcLane);
            float ev  = __expf(att);
            // M lanes accumulate; K lanes' accf is dead
            #pragma unroll
            for (int j = 0; j < 8; j++) accf[j] += f[j]*ev;
            den += ev;   // meaningful at K head-base lanes only
        }
    }

    if (lane >= 16) {
        __half2 p0 = __floats2half2_rn(accf[0], accf[1]);
        __half2 p1 = __floats2half2_rn(accf[2], accf[3]);
        __half2 p2 = __floats2half2_rn(accf[4], accf[5]);
        __half2 p3 = __floats2half2_rn(accf[6], accf[7]);
        uint4 ov;
        ov.x = *reinterpret_cast<uint32_t*>(&p0);
        ov.y = *reinterpret_cast<uint32_t*>(&p1);
        ov.z = *reinterpret_cast<uint32_t*>(&p2);
        ov.w = *reinterpret_cast<uint32_t*>(&p3);
        ((uint4*)(g_aggh + (size_t)wid*OUTF))[lane - 16] = ov;
    }
    if (lane < 16 && (lane & 3) == 0)
        g_den[(size_t)wid*HH + (lane >> 2)] = den;
}

// ---------------- node pass: gelu(agg/den) -> 1-term mma GEMM -> skip + LN ------
__global__ void __launch_bounds__(256, 2) node_mma_kernel(const float* __restrict__ x,
                                                          const float* __restrict__ ba,
                                                          const float* __restrict__ skip,
                                                          const float* __restrict__ lns,
                                                          const float* __restrict__ lnb,
                                                          float* __restrict__ out) {
    extern __shared__ char sm[];
    uint32_t su = smem_u32(sm);
    float* S = (float*)sm;        // reuse full smem after GEMM: [128][136] f32 = 69632B
    int tid = threadIdx.x;
    int w = tid >> 5, lane = tid & 31;
    int wm = w & 3, wn = w >> 2;

    int blk = blockIdx.x;
    int ntp = blk >= TILES;
    int tb  = blk - ntp*TILES;
    int base = tb*128; if (base > NN-128) base = NN-128;
    size_t nbase = (size_t)ntp*NN + base;

    // stage A = gelu(agg/den) -> fp16 smem
    #pragma unroll 4
    for (int j = 0; j < 16; j++) {
        int idx = tid + j*256;
        int row = idx >> 5, c4 = idx & 31;
        size_t nrow = nbase + row;
        uint2 av = ((const uint2*)(g_aggh + nrow*OUTF))[c4];
        float2 a01 = __half22float2(*(const __half2*)&av.x);
        float2 a23 = __half22float2(*(const __half2*)&av.y);
        float idn = 1.f / (g_den[nrow*HH + (c4 >> 3)] + 1e-16f);
        float4 v;
        v.x = a01.x*idn; v.y = a01.y*idn; v.z = a23.x*idn; v.w = a23.y*idn;
        v.x = 0.5f*v.x*(1.f + erff(v.x*0.70710678118654752f));
        v.y = 0.5f*v.y*(1.f + erff(v.y*0.70710678118654752f));
        v.z = 0.5f*v.z*(1.f + erff(v.z*0.70710678118654752f));
        v.w = 0.5f*v.w*(1.f + erff(v.w*0.70710678118654752f));
        __half2 h01 = __floats2half2_rn(v.x, v.y);
        __half2 h23 = __floats2half2_rn(v.z, v.w);
        *(uint32_t*)(sm + A_HI_OFF + row*ROWB + c4*8)     = *reinterpret_cast<uint32_t*>(&h01);
        *(uint32_t*)(sm + A_HI_OFF + row*ROWB + c4*8 + 4) = *reinterpret_cast<uint32_t*>(&h23);
    }
    __syncthreads();
    copy_B(sm, 3, ntp, tid);
    __syncthreads();

    float acc[2][8][4];
    #pragma unroll
    for (int mt = 0; mt < 2; mt++)
        #pragma unroll
        for (int nt = 0; nt < 8; nt++) {
            int col = wn*64 + nt*8 + 2*(lane & 3);
            float b0 = ba[ntp*OUTF + col], b1 = ba[ntp*OUTF + col + 1];
            acc[mt][nt][0] = b0; acc[mt][nt][1] = b1;
            acc[mt][nt][2] = b0; acc[mt][nt][3] = b1;
        }
    gemm_1term(su, w, lane, acc);
    __syncthreads();   // all warps done reading A+B regions before reuse as S

    // acc -> S [128][136] f32 (spans whole smem)
    #pragma unroll
    for (int mt = 0; mt < 2; mt++)
        #pragma unroll
        for (int nt = 0; nt < 8; nt++) {
            int row = wm*32 + mt*16 + (lane >> 2);
            int col = wn*64 + nt*8 + 2*(lane & 3);
            *(float2*)(S + row*136 + col)     = make_float2(acc[mt][nt][0], acc[mt][nt][1]);
            *(float2*)(S + (row+8)*136 + col) = make_float2(acc[mt][nt][2], acc[mt][nt][3]);
        }
    __syncthreads();

    // skip blend
    float alpha = 1.f / (1.f + __expf(-skip[ntp]));
    float beta  = 1.f - alpha;
    #pragma unroll 4
    for (int i = tid; i < 128*128; i += 256) {
        int r = i >> 7, c = i & 127;
        S[r*136 + c] = alpha*S[r*136 + c] + beta*x[(nbase + r)*INF + c];
    }
    __syncthreads();

    // layernorm: warp w rows 16w..16w+15
    for (int rr = 0; rr < 16; rr++) {
        int r = w*16 + rr;
        float s1 = 0.f, s2 = 0.f;
        #pragma unroll
        for (int c = lane; c < OUTF; c += 32) { float v = S[r*136 + c]; s1 += v; s2 += v*v; }
        #pragma unroll
        for (int off = 16; off; off >>= 1) {
            s1 += __shfl_xor_sync(0xffffffffu, s1, off);
            s2 += __shfl_xor_sync(0xffffffffu, s2, off);
        }
        float mean = s1 * (1.f/OUTF);
        float var  = s2 * (1.f/OUTF) - mean*mean;
        float inv  = rsqrtf(var + 1e-5f);
        #pragma unroll
        for (int c = lane; c < OUTF; c += 32)
            out[(nbase + r)*OUTF + c] = (S[r*136 + c] - mean)*inv*lns[ntp*OUTF + c]
                                        + lnb[ntp*OUTF + c];
    }
}

// ---------------- launch ----------------
extern "C" void kernel_launch(void* const* d_in, const int* in_sizes, int n_in,
                              void* d_out, int out_size) {
    const float* x     = (const float*)d_in[0];
    const int*   ei    = (const int*)  d_in[1];
    const float* Wk    = (const float*)d_in[2];
    const float* bk    = (const float*)d_in[3];
    const float* Wq    = (const float*)d_in[4];
    const float* bq    = (const float*)d_in[5];
    const float* Wm    = (const float*)d_in[6];
    const float* bm    = (const float*)d_in[7];
    const float* Wa    = (const float*)d_in[8];
    const float* ba    = (const float*)d_in[9];
    const float* w_att = (const float*)d_in[10];
    const float* w_msg = (const float*)d_in[11];
    const float* mu    = (const float*)d_in[12];
    const float* skip  = (const float*)d_in[13];
    const float* lns   = (const float*)d_in[14];
    const float* lnb   = (const float*)d_in[15];
    float* out = (float*)d_out;

    cudaFuncSetAttribute(proj_mma_kernel, cudaFuncAttributeMaxDynamicSharedMemorySize, SMEM_TOT);
    cudaFuncSetAttribute(node_mma_kernel, cudaFuncAttributeMaxDynamicSharedMemorySize, SMEM_TOT);

    prep_fold<<<256, 256>>>(Wk, bk, Wm, bm, w_att, w_msg, mu);
    prep_pack<<<512, 256>>>(Wq, Wa);
    hist_kernel<<<(2*EE + 255)/256, 256>>>(ei);
    scan_blocks<<<(2*NN + 1023)/1024, 1024>>>();
    scan_tops<<<1, 512>>>();
    add_offs<<<(2*NN + 1023)/1024, 1024>>>();
    scatter_kernel<<<(2*EE + 255)/256, 256>>>(ei);
    proj_mma_kernel<<<2*TILES, 256, SMEM_TOT>>>(x, bq);
    edge_node_kernel<<<(2*NN*32 + 255)/256, 256>>>();
    node_mma_kernel<<<2*TILES, 256, SMEM_TOT>>>(x, ba, skip, lns, lnb, out);
}

// round 17
// speedup vs baseline: 1.0748x; 1.0748x over previous
#include <cuda_runtime.h>
#include <cuda_fp16.h>
#include <math.h>
#include <stdint.h>

#define NN 200000
#define EE 1000000
#define INF 128
#define OUTF 128
#define HH 4
#define DKK 32
#define TILES 1563            // ceil(NN/128)

// smem layout (bytes): rows padded to 272B (conflict-free LDSM)
#define ROWB 272
#define A_HI_OFF 0
#define B_OFF    34816        // B right after A_HI (1-term GEMMs everywhere)
#define SMEM_TOT 69632

// ---------------- scratch (device globals; no allocation) ----------------
__device__ __half g_KMh[(size_t)2*NN*2*OUTF];   // K/M interleaved fp16: [2N][2][128]
__device__ __half g_Qh [(size_t)2*NN*OUTF];     // fp16
__device__ __half g_aggh[(size_t)2*NN*OUTF];    // fp16 aggregation buffer
__device__ float  g_den[(size_t)2*NN*HH];       // f32 softmax denominators
__device__ float  g_WkA[2*INF*OUTF];
__device__ float  g_bkA[2*OUTF];
__device__ float  g_WmM[2*INF*OUTF];
__device__ float  g_bmM[2*OUTF];
// packed fp16 weights, W^T layout [o][k]: [mat(4)][type(2)][128*128]
__device__ __half g_Wh[(size_t)4*2*16384];
// exact-dst sorted edges: srcs only, grouped by destination node (d-major)
__device__ uint32_t g_srt[(size_t)2*EE];
__device__ int    g_rank[(size_t)2*EE];        // per-edge rank within its dst
__device__ int    g_hist[2*NN];
__device__ int    g_cursor[2*NN + 1];
__device__ int    g_bsum[512];
__device__ int    g_bsumx[512];

#define MMA16816F16(acc, A0,A1,A2,A3, B0,B1) \
  asm volatile("mma.sync.aligned.m16n8k16.row.col.f32.f16.f16.f32 " \
    "{%0,%1,%2,%3}, {%4,%5,%6,%7}, {%8,%9}, {%0,%1,%2,%3};" \
    : "+f"((acc)[0]), "+f"((acc)[1]), "+f"((acc)[2]), "+f"((acc)[3]) \
    : "r"(A0), "r"(A1), "r"(A2), "r"(A3), "r"(B0), "r"(B1))

#define LDSM4(r0,r1,r2,r3,addr) \
  asm volatile("ldmatrix.sync.aligned.m8n8.x4.shared.b16 {%0,%1,%2,%3}, [%4];" \
    : "=r"(r0), "=r"(r1), "=r"(r2), "=r"(r3) : "r"(addr))

__device__ __forceinline__ uint32_t smem_u32(const void* p) {
    uint32_t a;
    asm("{ .reg .u64 t; cvta.to.shared.u64 t, %1; cvt.u32.u64 %0, t; }" : "=r"(a) : "l"(p));
    return a;
}

// ---------------- prep: fold w_att/w_msg (+ mu*scale) into projection weights
__global__ void prep_fold(const float* __restrict__ Wk, const float* __restrict__ bk,
                          const float* __restrict__ Wm, const float* __restrict__ bm,
                          const float* __restrict__ w_att, const float* __restrict__ w_msg,
                          const float* __restrict__ mu) {
    int idx = blockIdx.x*blockDim.x + threadIdx.x;     // 65536
    const int total = 2*INF*OUTF;
    int m   = idx / total;
    int rem = idx - m*total;
    int t   = rem / (INF*OUTF);
    int io  = rem - t*(INF*OUTF);
    int i   = io / OUTF;
    int o   = io - i*OUTF;
    int h   = o >> 5, f = o & 31;

    const float* W = m ? Wm : Wk;
    const float* R = m ? w_msg : w_att;
    const float* wrow = W + ((size_t)t*INF + i)*OUTF + h*DKK;
    const float* rr   = R + (((size_t)t*HH + h)*DKK)*DKK + f;
    float s = 0.f;
    #pragma unroll
    for (int d = 0; d < DKK; d++) s += wrow[d] * rr[(size_t)d*DKK];
    float fold = m ? 1.f : mu[t*HH + h] * 0.17677669529663687f;   // mu / sqrt(DK)
    (m ? g_WmM : g_WkA)[(size_t)t*INF*OUTF + io] = s * fold;

    if (i == 0) {
        const float* b = m ? bm : bk;
        float sb = 0.f;
        #pragma unroll
        for (int d = 0; d < DKK; d++) sb += b[t*OUTF + h*DKK + d] * rr[(size_t)d*DKK];
        (m ? g_bmM : g_bkA)[t*OUTF + o] = sb * fold;
    }
}

// pack 4 matrices (Kfold, Mfold, Q, A) per type as W^T [o][k] fp16; also zero hist
__global__ void prep_pack(const float* __restrict__ Wq, const float* __restrict__ Wa) {
    int idx = blockIdx.x*blockDim.x + threadIdx.x;   // 131072
    int mat = idx >> 15;
    int rem = idx & 32767;
    int t   = rem >> 14;
    int ok  = rem & 16383;
    int o   = ok >> 7;
    int k   = ok & 127;
    const float* W = (mat==0) ? g_WkA : (mat==1) ? g_WmM : (mat==2) ? Wq : Wa;
    float v = W[((size_t)t*INF + k)*OUTF + o];
    g_Wh[(size_t)(mat*2 + t)*16384 + ok] = __float2half(v);
    // zero per-dst histogram (grid-stride over 2N)
    for (int z = idx; z < 2*NN; z += 131072) g_hist[z] = 0;
}

// ---------------- exact-dst bucketing: histogram(+rank) -> scan -> rank scatter ----
__global__ void hist_kernel(const int* __restrict__ ei) {
    int i = blockIdx.x*blockDim.x + threadIdx.x;
    if (i >= 2*EE) return;
    int t = i >= EE;
    int e = i - t*EE;
    int dst = ei[(size_t)t*2*EE + EE + e];
    g_rank[i] = atomicAdd(&g_hist[(1-t)*NN + dst], 1);   // node key = d*NN + dst
}

__global__ void scan_blocks() {                // 391 blocks x 1024
    __shared__ int ss[1024];
    int tid = threadIdx.x;
    int gi = blockIdx.x*1024 + tid;
    int v = (gi < 2*NN) ? g_hist[gi] : 0;
    ss[tid] = v;
    __syncthreads();
    for (int off = 1; off < 1024; off <<= 1) {
        int u = (tid >= off) ? ss[tid-off] : 0;
        __syncthreads();
        ss[tid] += u;
        __syncthreads();
    }
    if (gi < 2*NN) g_cursor[gi] = ss[tid] - v;   // exclusive within block
    if (tid == 1023) g_bsum[blockIdx.x] = ss[1023];
}

__global__ void scan_tops() {                  // 1 block x 512 (covers 391 block sums)
    __shared__ int ss[512];
    int tid = threadIdx.x;
    int v = (tid < 391) ? g_bsum[tid] : 0;
    ss[tid] = v;
    __syncthreads();
    for (int off = 1; off < 512; off <<= 1) {
        int u = (tid >= off) ? ss[tid-off] : 0;
        __syncthreads();
        ss[tid] += u;
        __syncthreads();
    }
    g_bsumx[tid] = ss[tid] - v;                // exclusive
}

__global__ void add_offs() {                   // 391 blocks x 1024
    int tid = threadIdx.x;
    int gi = blockIdx.x*1024 + tid;
    if (gi < 2*NN)
        g_cursor[gi] += g_bsumx[blockIdx.x];
    if (gi == 0) g_cursor[2*NN] = 2*EE;
}

__global__ void scatter_kernel(const int* __restrict__ ei) {
    int i = blockIdx.x*blockDim.x + threadIdx.x;
    if (i >= 2*EE) return;
    int t = i >= EE;
    int e = i - t*EE;
    int src = ei[(size_t)t*2*EE + e];
    int dst = ei[(size_t)t*2*EE + EE + e];
    int pos = g_cursor[(1-t)*NN + dst] + g_rank[i];   // atomic-free
    g_srt[pos] = (uint32_t)src;
}

// copy one packed fp16 weight matrix (32KB) into the padded B buffer
__device__ __forceinline__ void copy_B(char* sm, int mat, int nt, int tid) {
    const uint4* src = (const uint4*)(g_Wh + (size_t)(mat*2 + nt) * 16384);
    #pragma unroll 2
    for (int i = tid; i < 2048; i += 256) {
        int row = i >> 4, chunk = i & 15;
        *(uint4*)(sm + B_OFF + row*ROWB + chunk*16) = src[i];
    }
}

// 1-term fp16 GEMM: acc += A*B
__device__ __forceinline__ void gemm_1term(uint32_t su, int w, int lane, float acc[2][8][4]) {
    int wm = w & 3, wn = w >> 2;
    int mat = lane >> 3, r8 = lane & 7;
    uint32_t aoff = (uint32_t)(wm*32 + (mat&1)*8 + r8)*ROWB + (mat>>1)*16;
    uint32_t boff = (uint32_t)(wn*64 + (mat>>1)*8 + r8)*ROWB + (mat&1)*16 + B_OFF;

    #pragma unroll
    for (int kk = 0; kk < 8; kk++) {
        uint32_t kb = kk*32;
        uint32_t A[2][4], B[8][2];
        #pragma unroll
        for (int mt = 0; mt < 2; mt++) {
            uint32_t ao = aoff + mt*16*ROWB + kb;
            LDSM4(A[mt][0], A[mt][1], A[mt][2], A[mt][3], su + A_HI_OFF + ao);
        }
        #pragma unroll
        for (int p = 0; p < 4; p++) {
            uint32_t bo = boff + p*16*ROWB + kb;
            LDSM4(B[2*p][0], B[2*p][1], B[2*p+1][0], B[2*p+1][1], su + bo);
        }
        #pragma unroll
        for (int mt = 0; mt < 2; mt++)
            #pragma unroll
            for (int nt = 0; nt < 8; nt++)
                MMA16816F16(acc[mt][nt], A[mt][0],A[mt][1],A[mt][2],A[mt][3], B[nt][0],B[nt][1]);
    }
}

// ---------------- proj: Ktr, Mtr, Q via 1-term mma.sync -> fp16 tables ----------------
__global__ void __launch_bounds__(256, 2) proj_mma_kernel(const float* __restrict__ x,
                                                          const float* __restrict__ bq) {
    extern __shared__ char sm[];
    uint32_t su = smem_u32(sm);
    int tid = threadIdx.x;
    int w = tid >> 5, lane = tid & 31;
    int wm = w & 3, wn = w >> 2;

    int blk = blockIdx.x;
    int ntp = blk >= TILES;
    int tb  = blk - ntp*TILES;
    int base = tb*128; if (base > NN-128) base = NN-128;
    size_t nbase = (size_t)ntp*NN + base;

    // stage A: x rows -> fp16 smem (single-rounded)
    #pragma unroll 4
    for (int j = 0; j < 16; j++) {
        int idx = tid + j*256;             // 4096 float4
        int row = idx >> 5, c4 = idx & 31;
        float4 v = ((const float4*)(x + (nbase + row)*INF))[c4];
        __half2 h01 = __floats2half2_rn(v.x, v.y);
        __half2 h23 = __floats2half2_rn(v.z, v.w);
        *(uint32_t*)(sm + A_HI_OFF + row*ROWB + c4*8)     = *reinterpret_cast<uint32_t*>(&h01);
        *(uint32_t*)(sm + A_HI_OFF + row*ROWB + c4*8 + 4) = *reinterpret_cast<uint32_t*>(&h23);
    }

    for (int m = 0; m < 3; m++) {
        __syncthreads();
        copy_B(sm, m, ntp, tid);
        __syncthreads();

        const float* bias = (m==0) ? g_bkA + ntp*OUTF
                          : (m==1) ? g_bmM + ntp*OUTF
                                   : bq    + ntp*OUTF;
        float acc[2][8][4];
        #pragma unroll
        for (int mt = 0; mt < 2; mt++)
            #pragma unroll
            for (int nt = 0; nt < 8; nt++) {
                int col = wn*64 + nt*8 + 2*(lane & 3);
                float b0 = bias[col], b1 = bias[col+1];
                acc[mt][nt][0] = b0; acc[mt][nt][1] = b1;
                acc[mt][nt][2] = b0; acc[mt][nt][3] = b1;
            }
        gemm_1term(su, w, lane, acc);
        __syncthreads();   // all warps done with B before staging reuses it

        // stage fp16 result into B buffer: 128 rows x 256B (+ ROWB pad)
        __half* H = (__half*)(sm + B_OFF);
        #pragma unroll
        for (int mt = 0; mt < 2; mt++)
            #pragma unroll
            for (int nt = 0; nt < 8; nt++) {
                int row = wm*32 + mt*16 + (lane >> 2);
                int col = wn*64 + nt*8 + 2*(lane & 3);
                *(__half2*)((char*)H + row*ROWB + col*2) =
                    __floats2half2_rn(acc[mt][nt][0], acc[mt][nt][1]);
                *(__half2*)((char*)H + (row+8)*ROWB + col*2) =
                    __floats2half2_rn(acc[mt][nt][2], acc[mt][nt][3]);
            }
        __syncthreads();

        // coalesced copy-out: 128 rows x 256B
        #pragma unroll
        for (int i = tid; i < 2048; i += 256) {
            int row = i >> 4, ch = i & 15;
            uint4 v = *(uint4*)((char*)H + row*ROWB + ch*16);
            __half* dst = (m == 2) ? g_Qh + (nbase + row)*OUTF + ch*8
                                   : g_KMh + ((nbase + row)*2 + m)*OUTF + ch*8;
            *(uint4*)dst = v;
        }
    }
}

// ---------------- edge pass: one warp per dst node, 2 edges/iter, 2-slot pipeline ----
__global__ void __launch_bounds__(256) edge_node_kernel() {
    int wid  = (blockIdx.x*blockDim.x + threadIdx.x) >> 5;   // node id [0, 2N)
    int lane = threadIdx.x & 31;
    if (wid >= 2*NN) return;
    int d = wid >= NN;
    int s = 1 - d;

    int start = g_cursor[wid];
    int end   = g_cursor[wid + 1];

    if (start == end) {   // empty segment: zeros
        ((uint2*)(g_aggh + (size_t)wid*OUTF))[lane] = make_uint2(0u, 0u);
        if ((lane & 7) == 0) g_den[(size_t)wid*HH + (lane >> 3)] = 0.f;
        return;
    }

    uint2 qv = ((const uint2*)(g_Qh + (size_t)wid*OUTF))[lane];
    float2 qa = __half22float2(*(const __half2*)&qv.x);
    float2 qb = __half22float2(*(const __half2*)&qv.y);

    float4 acc = make_float4(0.f, 0.f, 0.f, 0.f);
    float den = 0.f;

    const __half* KMbase = g_KMh + (size_t)s*NN*2*OUTF;

    // current pair in flight
    uint2 kc0, mc0, kc1, mc1;
    {
        int sc0 = (int)g_srt[start];
        const uint2* km0 = (const uint2*)(KMbase + (size_t)sc0*2*OUTF);
        kc0 = km0[lane]; mc0 = km0[32 + lane];
        if (start + 1 < end) {
            int sc1 = (int)g_srt[start + 1];
            const uint2* km1 = (const uint2*)(KMbase + (size_t)sc1*2*OUTF);
            kc1 = km1[lane]; mc1 = km1[32 + lane];
        }
    }

    for (int i = start; i < end; i += 2) {
        uint2 k0 = kc0, m0 = mc0, k1 = kc1, m1 = mc1;
        bool has1 = (i + 1 < end);
        // prefetch next pair
        if (i + 2 < end) {
            int sc0 = (int)g_srt[i + 2];
            const uint2* km0 = (const uint2*)(KMbase + (size_t)sc0*2*OUTF);
            kc0 = km0[lane]; mc0 = km0[32 + lane];
            if (i + 3 < end) {
                int sc1 = (int)g_srt[i + 3];
                const uint2* km1 = (const uint2*)(KMbase + (size_t)sc1*2*OUTF);
                kc1 = km1[lane]; mc1 = km1[32 + lane];
            }
        }

        // edge i
        {
            float2 ka = __half22float2(*(const __half2*)&k0.x);
            float2 kb = __half22float2(*(const __half2*)&k0.y);
            float p = ka.x*qa.x + ka.y*qa.y + kb.x*qb.x + kb.y*qb.y;
            p += __shfl_down_sync(0xffffffffu, p, 4, 8);
            p += __shfl_down_sync(0xffffffffu, p, 2, 8);
            p += __shfl_down_sync(0xffffffffu, p, 1, 8);
            float att = __shfl_sync(0xffffffffu, p, 0, 8);
            float ev  = __expf(att);
            float2 ma = __half22float2(*(const __half2*)&m0.x);
            float2 mb = __half22float2(*(const __half2*)&m0.y);
            acc.x += ma.x*ev; acc.y += ma.y*ev;
            acc.z += mb.x*ev; acc.w += mb.y*ev;
            den += ev;
        }
        // edge i+1
        if (has1) {
            float2 ka = __half22float2(*(const __half2*)&k1.x);
            float2 kb = __half22float2(*(const __half2*)&k1.y);
            float p = ka.x*qa.x + ka.y*qa.y + kb.x*qb.x + kb.y*qb.y;
            p += __shfl_down_sync(0xffffffffu, p, 4, 8);
            p += __shfl_down_sync(0xffffffffu, p, 2, 8);
            p += __shfl_down_sync(0xffffffffu, p, 1, 8);
            float att = __shfl_sync(0xffffffffu, p, 0, 8);
            float ev  = __expf(att);
            float2 ma = __half22float2(*(const __half2*)&m1.x);
            float2 mb = __half22float2(*(const __half2*)&m1.y);
            acc.x += ma.x*ev; acc.y += ma.y*ev;
            acc.z += mb.x*ev; acc.w += mb.y*ev;
            den += ev;
        }
    }

    // fp16 agg write (coalesced 256B/row)
    __half2 o01 = __floats2half2_rn(acc.x, acc.y);
    __half2 o23 = __floats2half2_rn(acc.z, acc.w);
    uint2 ov;
    ov.x = *reinterpret_cast<uint32_t*>(&o01);
    ov.y = *reinterpret_cast<uint32_t*>(&o23);
    ((uint2*)(g_aggh + (size_t)wid*OUTF))[lane] = ov;
    if ((lane & 7) == 0)
        g_den[(size_t)wid*HH + (lane >> 3)] = den;
}

// ---------------- node pass: gelu(agg/den) -> 1-term mma GEMM -> skip + LN ------
__global__ void __launch_bounds__(256, 2) node_mma_kernel(const float* __restrict__ x,
                                                          const float* __restrict__ ba,
                                                          const float* __restrict__ skip,
                                                          const float* __restrict__ lns,
                                                          const float* __restrict__ lnb,
                                                          float* __restrict__ out) {
    extern __shared__ char sm[];
    uint32_t su = smem_u32(sm);
    float* S = (float*)sm;        // reuse full smem after GEMM: [128][136] f32 = 69632B
    int tid = threadIdx.x;
    int w = tid >> 5, lane = tid & 31;
    int wm = w & 3, wn = w >> 2;

    int blk = blockIdx.x;
    int ntp = blk >= TILES;
    int tb  = blk - ntp*TILES;
    int base = tb*128; if (base > NN-128) base = NN-128;
    size_t nbase = (size_t)ntp*NN + base;

    // stage A = gelu(agg/den) -> fp16 smem
    #pragma unroll 4
    for (int j = 0; j < 16; j++) {
        int idx = tid + j*256;
        int row = idx >> 5, c4 = idx & 31;
        size_t nrow = nbase + row;
        uint2 av = ((const uint2*)(g_aggh + nrow*OUTF))[c4];
        float2 a01 = __half22float2(*(const __half2*)&av.x);
        float2 a23 = __half22float2(*(const __half2*)&av.y);
        float idn = 1.f / (g_den[nrow*HH + (c4 >> 3)] + 1e-16f);
        float4 v;
        v.x = a01.x*idn; v.y = a01.y*idn; v.z = a23.x*idn; v.w = a23.y*idn;
        v.x = 0.5f*v.x*(1.f + erff(v.x*0.70710678118654752f));
        v.y = 0.5f*v.y*(1.f + erff(v.y*0.70710678118654752f));
        v.z = 0.5f*v.z*(1.f + erff(v.z*0.70710678118654752f));
        v.w = 0.5f*v.w*(1.f + erff(v.w*0.70710678118654752f));
        __half2 h01 = __floats2half2_rn(v.x, v.y);
        __half2 h23 = __floats2half2_rn(v.z, v.w);
        *(uint32_t*)(sm + A_HI_OFF + row*ROWB + c4*8)     = *reinterpret_cast<uint32_t*>(&h01);
        *(uint32_t*)(sm + A_HI_OFF + row*ROWB + c4*8 + 4) = *reinterpret_cast<uint32_t*>(&h23);
    }
    __syncthreads();
    copy_B(sm, 3, ntp, tid);
    __syncthreads();

    float acc[2][8][4];
    #pragma unroll
    for (int mt = 0; mt < 2; mt++)
        #pragma unroll
        for (int nt = 0; nt < 8; nt++) {
            int col = wn*64 + nt*8 + 2*(lane & 3);
            float b0 = ba[ntp*OUTF + col], b1 = ba[ntp*OUTF + col + 1];
            acc[mt][nt][0] = b0; acc[mt][nt][1] = b1;
            acc[mt][nt][2] = b0; acc[mt][nt][3] = b1;
        }
    gemm_1term(su, w, lane, acc);
    __syncthreads();   // all warps done reading A+B regions before reuse as S

    // acc -> S [128][136] f32 (spans whole smem)
    #pragma unroll
    for (int mt = 0; mt < 2; mt++)
        #pragma unroll
        for (int nt = 0; nt < 8; nt++) {
            int row = wm*32 + mt*16 + (lane >> 2);
            int col = wn*64 + nt*8 + 2*(lane & 3);
            *(float2*)(S + row*136 + col)     = make_float2(acc[mt][nt][0], acc[mt][nt][1]);
            *(float2*)(S + (row+8)*136 + col) = make_float2(acc[mt][nt][2], acc[mt][nt][3]);
        }
    __syncthreads();

    // skip blend
    float alpha = 1.f / (1.f + __expf(-skip[ntp]));
    float beta  = 1.f - alpha;
    #pragma unroll 4
    for (int i = tid; i < 128*128; i += 256) {
        int r = i >> 7, c = i & 127;
        S[r*136 + c] = alpha*S[r*136 + c] + beta*x[(nbase + r)*INF + c];
    }
    __syncthreads();

    // layernorm: warp w rows 16w..16w+15
    for (int rr = 0; rr < 16; rr++) {
        int r = w*16 + rr;
        float s1 = 0.f, s2 = 0.f;
        #pragma unroll
        for (int c = lane; c < OUTF; c += 32) { float v = S[r*136 + c]; s1 += v; s2 += v*v; }
        #pragma unroll
        for (int off = 16; off; off >>= 1) {
            s1 += __shfl_xor_sync(0xffffffffu, s1, off);
            s2 += __shfl_xor_sync(0xffffffffu, s2, off);
        }
        float mean = s1 * (1.f/OUTF);
        float var  = s2 * (1.f/OUTF) - mean*mean;
        float inv  = rsqrtf(var + 1e-5f);
        #pragma unroll
        for (int c = lane; c < OUTF; c += 32)
            out[(nbase + r)*OUTF + c] = (S[r*136 + c] - mean)*inv*lns[ntp*OUTF + c]
                                        + lnb[ntp*OUTF + c];
    }
}

// ---------------- launch ----------------
extern "C" void kernel_launch(void* const* d_in, const int* in_sizes, int n_in,
                              void* d_out, int out_size) {
    const float* x     = (const float*)d_in[0];
    const int*   ei    = (const int*)  d_in[1];
    const float* Wk    = (const float*)d_in[2];
    const float* bk    = (const float*)d_in[3];
    const float* Wq    = (const float*)d_in[4];
    const float* bq    = (const float*)d_in[5];
    const float* Wm    = (const float*)d_in[6];
    const float* bm    = (const float*)d_in[7];
    const float* Wa    = (const float*)d_in[8];
    const float* ba    = (const float*)d_in[9];
    const float* w_att = (const float*)d_in[10];
    const float* w_msg = (const float*)d_in[11];
    const float* mu    = (const float*)d_in[12];
    const float* skip  = (const float*)d_in[13];
    const float* lns   = (const float*)d_in[14];
    const float* lnb   = (const float*)d_in[15];
    float* out = (float*)d_out;

    cudaFuncSetAttribute(proj_mma_kernel, cudaFuncAttributeMaxDynamicSharedMemorySize, SMEM_TOT);
    cudaFuncSetAttribute(node_mma_kernel, cudaFuncAttributeMaxDynamicSharedMemorySize, SMEM_TOT);

    prep_fold<<<256, 256>>>(Wk, bk, Wm, bm, w_att, w_msg, mu);
    prep_pack<<<512, 256>>>(Wq, Wa);
    hist_kernel<<<(2*EE + 255)/256, 256>>>(ei);
    scan_blocks<<<(2*NN + 1023)/1024, 1024>>>();
    scan_tops<<<1, 512>>>();
    add_offs<<<(2*NN + 1023)/1024, 1024>>>();
    scatter_kernel<<<(2*EE + 255)/256, 256>>>(ei);
    proj_mma_kernel<<<2*TILES, 256, SMEM_TOT>>>(x, bq);
    edge_node_kernel<<<(2*NN*32 + 255)/256, 256>>>();
    node_mma_kernel<<<2*TILES, 256, SMEM_TOT>>>(x, ba, skip, lns, lnb, out);
}